// round 5
// baseline (speedup 1.0000x reference)
#include <cuda_runtime.h>
#include <cuda_bf16.h>

// NonMaximaSuppression2d: x (8, 64, 256, 256) fp32.
// out[p] = x[p] if x[p] > max(0, 8 replicate-padded neighbors) else 0.
//
// One warp = FOUR adjacent 256-wide output rows; each lane owns 8 columns
// (2x float4). 12 independent LDG.128 per thread (rows y-1..y+4), then
// all compute. Vertical halo amortization: 6 rows loaded per 4 produced
// (1.5x read amp) -> ~40% fewer l1tex wavefronts/byte than 2-row version.

#define H 256
#define W 256
#define WARPS_PER_BLOCK 8
#define NIMG (8 * 64)            // 512 images
#define QUADS_PER_IMG (H / 4)    // 64 row-quads

__device__ __forceinline__ void load_row(const float* __restrict__ row,
                                         int lane, float v[8])
{
    const float4* p = (const float4*)row + lane * 2;
    float4 a = __ldg(p);
    float4 b = __ldg(p + 1);
    v[0] = a.x; v[1] = a.y; v[2] = a.z; v[3] = a.w;
    v[4] = b.x; v[5] = b.y; v[6] = b.z; v[7] = b.w;
}

// h2[j] = max(v[j-1], v[j+1]) with replicate padding at image edges.
__device__ __forceinline__ void calc_h2(const float v[8], int lane, float h2[8])
{
    float lf = __shfl_up_sync(0xffffffffu, v[7], 1);
    if (lane == 0) lf = v[0];                 // replicate col 0
    float rt = __shfl_down_sync(0xffffffffu, v[0], 1);
    if (lane == 31) rt = v[7];                // replicate col 255

    h2[0] = fmaxf(lf,   v[1]);
#pragma unroll
    for (int j = 1; j < 7; j++)
        h2[j] = fmaxf(v[j-1], v[j+1]);
    h2[7] = fmaxf(v[6], rt);
}

__device__ __forceinline__ void store_row(float* __restrict__ row, int lane,
                                          const float o[8])
{
    float4* p = (float4*)row + lane * 2;
    p[0] = make_float4(o[0], o[1], o[2], o[3]);
    p[1] = make_float4(o[4], o[5], o[6], o[7]);
}

__global__ __launch_bounds__(32 * WARPS_PER_BLOCK, 3)
void nms2d_kernel(const float* __restrict__ x, float* __restrict__ out)
{
    const int warp = threadIdx.x >> 5;
    const int lane = threadIdx.x & 31;
    const int r    = blockIdx.x * WARPS_PER_BLOCK + warp;  // global quad id
    const int b    = r >> 6;                               // image
    const int yq   = (r & 63) * 4;                         // first output row

    const float* __restrict__ base = x + (size_t)b * (H * W);

    const int ya = (yq > 0) ? yq - 1 : 0;          // top halo
    const int yd = (yq + 4 < H) ? yq + 4 : H - 1;  // bottom halo

    // 6 rows = 12 independent LDG.128, all issued before dependent math.
    float v[6][8];
    load_row(base + (size_t)ya       * W, lane, v[0]);
    load_row(base + (size_t)yq       * W, lane, v[1]);
    load_row(base + (size_t)(yq + 1) * W, lane, v[2]);
    load_row(base + (size_t)(yq + 2) * W, lane, v[3]);
    load_row(base + (size_t)(yq + 3) * W, lane, v[4]);
    load_row(base + (size_t)yd       * W, lane, v[5]);

    float h2[6][8];
#pragma unroll
    for (int i = 0; i < 6; i++)
        calc_h2(v[i], lane, h2[i]);

    float* obase = out + (size_t)b * (H * W) + (size_t)yq * W;

#pragma unroll
    for (int i = 0; i < 4; i++) {       // output row i uses rows i, i+1, i+2
        float o[8];
#pragma unroll
        for (int j = 0; j < 8; j++) {
            const float h3t = fmaxf(h2[i][j],     v[i][j]);     // top 3-max
            const float h3b = fmaxf(h2[i + 2][j], v[i + 2][j]); // bottom 3-max
            float mx = fmaxf(h2[i + 1][j], 0.0f);               // mid, 0-seeded
            mx = fmaxf(mx, fmaxf(h3t, h3b));
            const float c = v[i + 1][j];
            o[j] = (c > mx) ? c : 0.0f;
        }
        store_row(obase + (size_t)i * W, lane, o);
    }
}

extern "C" void kernel_launch(void* const* d_in, const int* in_sizes, int n_in,
                              void* d_out, int out_size)
{
    const float* x = (const float*)d_in[0];
    float* out = (float*)d_out;

    const int total_quads = NIMG * QUADS_PER_IMG;        // 32768 warps
    const int blocks = total_quads / WARPS_PER_BLOCK;    // 4096 blocks
    nms2d_kernel<<<blocks, 32 * WARPS_PER_BLOCK>>>(x, out);
}

// round 6
// speedup vs baseline: 1.0360x; 1.0360x over previous
#include <cuda_runtime.h>
#include <cuda_bf16.h>

// NonMaximaSuppression2d: x (8, 64, 256, 256) fp32.
// out[p] = x[p] if x[p] > max(0, 8 replicate-padded neighbors) else 0.
//
// One warp = TWO adjacent 256-wide output rows; lane owns 8 cols (2x float4).
// 8 independent LDG.128 per thread (rows y-1..y+2), MLP=8.
// Column-max formulation:
//   q02 = max(v0,v2), q13 = max(v1,v3)
//   cm_a = max(v0,v1,v2) = max(q02,v1);  cm_b = max(v1,v2,v3) = max(q13,v2)
//   out_a = v1 > max(cm_a[j-1], cm_a[j+1], q02[j], 0) ? v1 : 0
//   out_b = v2 > max(cm_b[j-1], cm_b[j+1], q13[j], 0) ? v2 : 0
// Only 4 shuffles/warp (on cm rows), fewer fmax, v0/v3 die early.
// __launch_bounds__(256,5) caps regs at 51 -> 40 warps/SM (62.5% occ).

#define H 256
#define W 256
#define WARPS_PER_BLOCK 8
#define NIMG (8 * 64)            // 512 images
#define PAIRS_PER_IMG (H / 2)    // 128 row-pairs

__device__ __forceinline__ void load_row(const float* __restrict__ row,
                                         int lane, float v[8])
{
    const float4* p = (const float4*)row + lane * 2;
    float4 a = __ldg(p);
    float4 b = __ldg(p + 1);
    v[0] = a.x; v[1] = a.y; v[2] = a.z; v[3] = a.w;
    v[4] = b.x; v[5] = b.y; v[6] = b.z; v[7] = b.w;
}

// Horizontal 2-sided neighbor max of cm with replicate clamp at image edges:
// n[j] = max(cm[j-1], cm[j+1]), cm[-1]->cm[0], cm[256]->cm[255].
__device__ __forceinline__ void hnb(const float cm[8], int lane, float n[8])
{
    float lf = __shfl_up_sync(0xffffffffu, cm[7], 1);
    if (lane == 0) lf = cm[0];                // replicate col 0
    float rt = __shfl_down_sync(0xffffffffu, cm[0], 1);
    if (lane == 31) rt = cm[7];               // replicate col 255

    n[0] = fmaxf(lf,    cm[1]);
#pragma unroll
    for (int j = 1; j < 7; j++)
        n[j] = fmaxf(cm[j-1], cm[j+1]);
    n[7] = fmaxf(cm[6], rt);
}

__global__ __launch_bounds__(32 * WARPS_PER_BLOCK, 5)
void nms2d_kernel(const float* __restrict__ x, float* __restrict__ out)
{
    const int warp = threadIdx.x >> 5;
    const int lane = threadIdx.x & 31;
    const int r    = blockIdx.x * WARPS_PER_BLOCK + warp;  // global row-pair id
    const int b    = r >> 7;                               // image
    const int yp   = (r & 127) * 2;                        // first output row

    const float* __restrict__ base = x + (size_t)b * (H * W);

    const int ya = (yp > 0) ? yp - 1 : 0;          // top halo
    const int yd = (yp + 2 < H) ? yp + 2 : H - 1;  // bottom halo

    // 8 independent LDG.128 — all issued before any dependent math.
    float v0[8], v1[8], v2[8], v3[8];
    load_row(base + (size_t)ya       * W, lane, v0);
    load_row(base + (size_t)yp       * W, lane, v1);
    load_row(base + (size_t)(yp + 1) * W, lane, v2);
    load_row(base + (size_t)yd       * W, lane, v3);

    // Column maxes; v0 and v3 die here.
    float q02[8], q13[8], cma[8], cmb[8];
#pragma unroll
    for (int j = 0; j < 8; j++) {
        q02[j] = fmaxf(v0[j], v2[j]);
        q13[j] = fmaxf(v1[j], v3[j]);
        cma[j] = fmaxf(q02[j], v1[j]);
        cmb[j] = fmaxf(q13[j], v2[j]);
    }

    float na[8], nb[8];
    hnb(cma, lane, na);
    hnb(cmb, lane, nb);

    float* obase = out + (size_t)b * (H * W);

    float oa[8];
#pragma unroll
    for (int j = 0; j < 8; j++) {
        float mx = fmaxf(na[j], fmaxf(q02[j], 0.0f));
        oa[j] = (v1[j] > mx) ? v1[j] : 0.0f;
    }
    {
        float4* pa = (float4*)(obase + (size_t)yp * W) + lane * 2;
        pa[0] = make_float4(oa[0], oa[1], oa[2], oa[3]);
        pa[1] = make_float4(oa[4], oa[5], oa[6], oa[7]);
    }

    float ob[8];
#pragma unroll
    for (int j = 0; j < 8; j++) {
        float mx = fmaxf(nb[j], fmaxf(q13[j], 0.0f));
        ob[j] = (v2[j] > mx) ? v2[j] : 0.0f;
    }
    {
        float4* pb = (float4*)(obase + (size_t)(yp + 1) * W) + lane * 2;
        pb[0] = make_float4(ob[0], ob[1], ob[2], ob[3]);
        pb[1] = make_float4(ob[4], ob[5], ob[6], ob[7]);
    }
}

extern "C" void kernel_launch(void* const* d_in, const int* in_sizes, int n_in,
                              void* d_out, int out_size)
{
    const float* x = (const float*)d_in[0];
    float* out = (float*)d_out;

    const int total_pairs = NIMG * PAIRS_PER_IMG;        // 65536 warps
    const int blocks = total_pairs / WARPS_PER_BLOCK;    // 8192 blocks
    nms2d_kernel<<<blocks, 32 * WARPS_PER_BLOCK>>>(x, out);
}

// round 7
// speedup vs baseline: 1.0368x; 1.0007x over previous
#include <cuda_runtime.h>
#include <cuda_bf16.h>

// NonMaximaSuppression2d: x (8, 64, 256, 256) fp32.
// out[p] = x[p] if x[p] > max(0, 8 replicate-padded neighbors) else 0.
//
// One warp = TWO adjacent 256-wide output rows; lane owns 8 cols (2x float4).
// 8 independent LDG.128 per thread (rows y-1..y+2), MLP=8.
// Column-max formulation (4 shuffles/warp).
// Output stores use __stcs (evict-first): output is never re-read, so it
// must not evict the L2-resident input (input ~134MB vs 126MB L2; it stays
// hot across graph replays and serves the 3x vertical re-reads in-launch).

#define H 256
#define W 256
#define WARPS_PER_BLOCK 8
#define NIMG (8 * 64)            // 512 images
#define PAIRS_PER_IMG (H / 2)    // 128 row-pairs

__device__ __forceinline__ void load_row(const float* __restrict__ row,
                                         int lane, float v[8])
{
    const float4* p = (const float4*)row + lane * 2;
    float4 a = __ldg(p);
    float4 b = __ldg(p + 1);
    v[0] = a.x; v[1] = a.y; v[2] = a.z; v[3] = a.w;
    v[4] = b.x; v[5] = b.y; v[6] = b.z; v[7] = b.w;
}

// n[j] = max(cm[j-1], cm[j+1]) with replicate clamp at image edges.
__device__ __forceinline__ void hnb(const float cm[8], int lane, float n[8])
{
    float lf = __shfl_up_sync(0xffffffffu, cm[7], 1);
    if (lane == 0) lf = cm[0];                // replicate col 0
    float rt = __shfl_down_sync(0xffffffffu, cm[0], 1);
    if (lane == 31) rt = cm[7];               // replicate col 255

    n[0] = fmaxf(lf,    cm[1]);
#pragma unroll
    for (int j = 1; j < 7; j++)
        n[j] = fmaxf(cm[j-1], cm[j+1]);
    n[7] = fmaxf(cm[6], rt);
}

__global__ __launch_bounds__(32 * WARPS_PER_BLOCK, 5)
void nms2d_kernel(const float* __restrict__ x, float* __restrict__ out)
{
    const int warp = threadIdx.x >> 5;
    const int lane = threadIdx.x & 31;
    const int r    = blockIdx.x * WARPS_PER_BLOCK + warp;  // global row-pair id
    const int b    = r >> 7;                               // image
    const int yp   = (r & 127) * 2;                        // first output row

    const float* __restrict__ base = x + (size_t)b * (H * W);

    const int ya = (yp > 0) ? yp - 1 : 0;          // top halo
    const int yd = (yp + 2 < H) ? yp + 2 : H - 1;  // bottom halo

    // 8 independent LDG.128 — all issued before any dependent math.
    float v0[8], v1[8], v2[8], v3[8];
    load_row(base + (size_t)ya       * W, lane, v0);
    load_row(base + (size_t)yp       * W, lane, v1);
    load_row(base + (size_t)(yp + 1) * W, lane, v2);
    load_row(base + (size_t)yd       * W, lane, v3);

    // Column maxes; v0 and v3 die here.
    float q02[8], q13[8], cma[8], cmb[8];
#pragma unroll
    for (int j = 0; j < 8; j++) {
        q02[j] = fmaxf(v0[j], v2[j]);
        q13[j] = fmaxf(v1[j], v3[j]);
        cma[j] = fmaxf(q02[j], v1[j]);
        cmb[j] = fmaxf(q13[j], v2[j]);
    }

    float na[8], nb[8];
    hnb(cma, lane, na);
    hnb(cmb, lane, nb);

    float* obase = out + (size_t)b * (H * W);

    float oa[8];
#pragma unroll
    for (int j = 0; j < 8; j++) {
        float mx = fmaxf(na[j], fmaxf(q02[j], 0.0f));
        oa[j] = (v1[j] > mx) ? v1[j] : 0.0f;
    }
    {
        float4* pa = (float4*)(obase + (size_t)yp * W) + lane * 2;
        __stcs(pa,     make_float4(oa[0], oa[1], oa[2], oa[3]));
        __stcs(pa + 1, make_float4(oa[4], oa[5], oa[6], oa[7]));
    }

    float ob[8];
#pragma unroll
    for (int j = 0; j < 8; j++) {
        float mx = fmaxf(nb[j], fmaxf(q13[j], 0.0f));
        ob[j] = (v2[j] > mx) ? v2[j] : 0.0f;
    }
    {
        float4* pb = (float4*)(obase + (size_t)(yp + 1) * W) + lane * 2;
        __stcs(pb,     make_float4(ob[0], ob[1], ob[2], ob[3]));
        __stcs(pb + 1, make_float4(ob[4], ob[5], ob[6], ob[7]));
    }
}

extern "C" void kernel_launch(void* const* d_in, const int* in_sizes, int n_in,
                              void* d_out, int out_size)
{
    const float* x = (const float*)d_in[0];
    float* out = (float*)d_out;

    const int total_pairs = NIMG * PAIRS_PER_IMG;        // 65536 warps
    const int blocks = total_pairs / WARPS_PER_BLOCK;    // 8192 blocks
    nms2d_kernel<<<blocks, 32 * WARPS_PER_BLOCK>>>(x, out);
}